// round 12
// baseline (speedup 1.0000x reference)
#include <cuda_runtime.h>
#include <cuda_bf16.h>
#include <cstdint>

#define NN   4
#define CC   256
#define OO   256
#define HH   96
#define WW   96
#define HW   9216
#define NHW  36864

#define BM   128
#define NTHR 512
#define NCHUNK 72           // 9 taps (inner) x 8 c-subchunks (outer)

// GEMM smem (bytes). Tiles use 80B row pitch (40 bf16): ldmatrix 8-row phases
// hit banks {0,20,8,28,16,4,24,12}*4w -> conflict-free. Two pipeline stages.
#define SM_WT    0                      // float4 [9][128]  = 18432
#define SM_IT    18432                  // ushort4[9][128]  =  9216
#define SM_ST0   27648
#define STAGE_SZ 61440                  // AH 10240 | AL 10240 | BH 20480 | BL 20480
#define O_AH 0
#define O_AL 10240
#define O_BH 20480
#define O_BL 40960
#define SMEM_GEMM (SM_ST0 + 2*STAGE_SZ) // 150528

// ---- scratch globals ----
__device__ __align__(256) float         g_off[NN * 18 * HW];
__device__ __align__(256) __nv_bfloat16 g_Bh[OO * 2304];
__device__ __align__(256) __nv_bfloat16 g_Bl[OO * 2304];
__device__ __align__(256) float2        g_wo2[CC * 81];
__device__ __align__(256) float         g_xt[(size_t)NN * HW * 256];  // pixel-major x
__device__ __align__(256) float         g_y[(size_t)NHW * 256];       // [gpix][o]
__device__ float g_sum[OO];
__device__ float g_sq[OO];

// ---- helpers ----
__device__ __forceinline__ uint32_t smem_addr(const void* p) {
    uint32_t a;
    asm("{ .reg .u64 t; cvta.to.shared.u64 t, %1; cvt.u32.u64 %0, t; }" : "=r"(a) : "l"(p));
    return a;
}
__device__ __forceinline__ void cpa16(uint32_t d, const void* s) {
    asm volatile("cp.async.cg.shared.global [%0], [%1], 16;" :: "r"(d), "l"(s) : "memory");
}
__device__ __forceinline__ void cpa8(uint32_t d, const void* s) {
    asm volatile("cp.async.ca.shared.global [%0], [%1], 8;" :: "r"(d), "l"(s) : "memory");
}
__device__ __forceinline__ void cpa4z(uint32_t d, const void* s, int sz) {
    asm volatile("cp.async.ca.shared.global [%0], [%1], 4, %2;" :: "r"(d), "l"(s), "r"(sz) : "memory");
}
__device__ __forceinline__ void cpa_commit() {
    asm volatile("cp.async.commit_group;" ::: "memory");
}
__device__ __forceinline__ void cpa_wait0() {
    asm volatile("cp.async.wait_group 0;" ::: "memory");
}
__device__ __forceinline__ void ldsm4(uint32_t &r0, uint32_t &r1, uint32_t &r2, uint32_t &r3,
                                      uint32_t addr) {
    asm volatile("ldmatrix.sync.aligned.m8n8.x4.shared.b16 {%0,%1,%2,%3}, [%4];"
                 : "=r"(r0), "=r"(r1), "=r"(r2), "=r"(r3) : "r"(addr));
}
__device__ __forceinline__ uint32_t pkbf(__nv_bfloat16 a, __nv_bfloat16 b) {
    return (uint32_t)__bfloat16_as_ushort(a) | ((uint32_t)__bfloat16_as_ushort(b) << 16);
}
__device__ __forceinline__ unsigned long long pack2(float x, float y) {
    unsigned long long r;
    asm("mov.b64 %0, {%1, %2};" : "=l"(r) : "f"(x), "f"(y));
    return r;
}
__device__ __forceinline__ void unpack2(unsigned long long v, float &x, float &y) {
    asm("mov.b64 {%0, %1}, %2;" : "=f"(x), "=f"(y) : "l"(v));
}
__device__ __forceinline__ void ffma2(unsigned long long &d, unsigned long long a,
                                      unsigned long long b) {
    asm("fma.rn.f32x2 %0, %1, %2, %0;" : "+l"(d) : "l"(a), "l"(b));
}
__device__ __forceinline__ void mma_bf16(float* d, const uint32_t* a,
                                         uint32_t b0, uint32_t b1) {
    asm volatile(
        "mma.sync.aligned.m16n8k16.row.col.f32.bf16.bf16.f32 "
        "{%0,%1,%2,%3}, {%4,%5,%6,%7}, {%8,%9}, {%0,%1,%2,%3};"
        : "+f"(d[0]), "+f"(d[1]), "+f"(d[2]), "+f"(d[3])
        : "r"(a[0]), "r"(a[1]), "r"(a[2]), "r"(a[3]), "r"(b0), "r"(b1));
}

// ---------------- kernel 1: weight prep (+ zero BN accumulators) ----------------
__global__ void prep_kernel(const float* __restrict__ w_dcn,
                            const float* __restrict__ w_off) {
    int e = blockIdx.x * blockDim.x + threadIdx.x;   // 589824 exact
    {
        int o = e / 2304, r = e - o * 2304;
        int kt = r >> 8, c = r & 255;
        float v = w_dcn[(o * CC + c) * 9 + kt];
        __nv_bfloat16 hi = __float2bfloat16(v);
        g_Bh[e] = hi;
        g_Bl[e] = __float2bfloat16(v - __bfloat162float(hi));
    }
    if (e < CC * 81) {
        int c = e / 81, r = e - c * 81;
        int t = r / 9, p = r - t * 9;
        g_wo2[e] = make_float2(w_off[(2 * p) * 2304 + c * 9 + t],
                               w_off[(2 * p + 1) * 2304 + c * 9 + t]);
    }
    if (e < OO) { g_sum[e] = 0.f; g_sq[e] = 0.f; }
}

// ---------------- kernel 1b: transpose x -> pixel-major [n][pix][c] ----------------
__global__ __launch_bounds__(256) void transpose_kernel(const float* __restrict__ x) {
    __shared__ float t[32][33];
    int p0 = blockIdx.x * 32;
    int c0 = blockIdx.y * 32;
    int n  = blockIdx.z;
    int tx = threadIdx.x & 31, ty = threadIdx.x >> 5;
#pragma unroll
    for (int j = 0; j < 4; j++) {
        int c = c0 + ty + j * 8;
        t[ty + j * 8][tx] = x[((size_t)(n * CC + c)) * HW + p0 + tx];
    }
    __syncthreads();
#pragma unroll
    for (int j = 0; j < 4; j++) {
        int p = p0 + ty + j * 8;
        g_xt[((size_t)n * HW + p) * 256 + c0 + tx] = t[tx][ty + j * 8];
    }
}

// ---------------- kernel 2: offset conv, cp.async double-buffered ----------------
__global__ __launch_bounds__(256) void offset_conv_kernel(
    const float* __restrict__ x, const float* __restrict__ b_off)
{
    __shared__ float xs[2][4][18][19];
    __shared__ unsigned long long ws[2][4][81];
    int n  = blockIdx.z;
    int h0 = blockIdx.y * 16, w0 = blockIdx.x * 16;
    int tid = threadIdx.x;
    int ty = tid >> 4, tx = tid & 15;
    uint32_t xs_b = smem_addr(&xs[0][0][0][0]);
    uint32_t ws_b = smem_addr(&ws[0][0][0]);
    const unsigned long long* wo2 = (const unsigned long long*)g_wo2;

    unsigned long long acc[9];
#pragma unroll
    for (int p = 0; p < 9; p++) acc[p] = 0ull;

    auto prefetch = [&](int cg, int st) {
        int cb = cg * 4;
        for (int i = tid; i < 1296; i += 256) {
            int cl = i / 324, r2 = i - cl * 324;
            int r = r2 / 18, q = r2 - r * 18;
            int hh = h0 - 1 + r, wp = w0 - 1 + q;
            int ok = ((unsigned)hh < (unsigned)HH && (unsigned)wp < (unsigned)WW) ? 4 : 0;
            int hc = min(max(hh, 0), HH - 1), wc = min(max(wp, 0), WW - 1);
            cpa4z(xs_b + (uint32_t)(((st * 4 + cl) * 342) + r * 19 + q) * 4,
                  &x[((n * CC + cb + cl) * HH + hc) * WW + wc], ok);
        }
        for (int i = tid; i < 324; i += 256) {
            int cl = i / 81, r = i - cl * 81;
            cpa8(ws_b + (uint32_t)((st * 4 + cl) * 81 + r) * 8, &wo2[(cb + cl) * 81 + r]);
        }
        cpa_commit();
    };

    prefetch(0, 0);
    cpa_wait0();
    __syncthreads();

    for (int cg = 0; cg < 64; cg++) {
        int st = cg & 1;
        if (cg < 63) prefetch(cg + 1, st ^ 1);
#pragma unroll
        for (int cl = 0; cl < 4; cl++) {
            float xv[9];
#pragma unroll
            for (int t = 0; t < 9; t++) xv[t] = xs[st][cl][ty + t / 3][tx + t % 3];
#pragma unroll
            for (int t = 0; t < 9; t++) {
                unsigned long long bb = pack2(xv[t], xv[t]);
#pragma unroll
                for (int p = 0; p < 9; p++) ffma2(acc[p], ws[st][cl][t * 9 + p], bb);
            }
        }
        cpa_wait0();
        __syncthreads();
    }
    int h = h0 + ty, w = w0 + tx;
#pragma unroll
    for (int p = 0; p < 9; p++) {
        float a0, a1;
        unpack2(acc[p], a0, a1);
        g_off[((n * 18 + 2 * p) * HH + h) * WW + w]     = a0 + b_off[2 * p];
        g_off[((n * 18 + 2 * p + 1) * HH + h) * WW + w] = a1 + b_off[2 * p + 1];
    }
}

// ---------------- kernel 3: HMMA GEMM, float4 gather + ldmatrix pipeline ----
__global__ __launch_bounds__(NTHR, 1) void dcn_gemm_kernel(const float* __restrict__ X)
{
    extern __shared__ __align__(128) char smem[];
    float4*  wt = (float4*)(smem + SM_WT);
    ushort4* it = (ushort4*)(smem + SM_IT);
    uint32_t sb = smem_addr(smem);

    int tid = threadIdx.x;
    int wid = tid >> 5, lid = tid & 31;
    int m0   = blockIdx.x * BM;
    int n    = m0 / HW;
    int pix0 = m0 - n * HW;

    // ---- bilinear tables ----
    for (int e = tid; e < BM * 9; e += NTHR) {
        int k = e / BM, mi = e - k * BM;
        int pix = pix0 + mi;
        int h = pix / WW, w = pix - h * WW;
        float dy = g_off[((n * 18 + 2 * k) * HH + h) * WW + w];
        float dx = g_off[((n * 18 + 2 * k + 1) * HH + h) * WW + w];
        float py = (float)(h + k / 3 - 1) + dy;
        float px = (float)(w + (k % 3) - 1) + dx;
        float fy = floorf(py), fx = floorf(px);
        int y0 = (int)fy, x0 = (int)fx;
        float wy = py - fy, wx = px - fx;
        float m00 = ((unsigned)y0 < HH && (unsigned)x0 < WW) ? 1.f : 0.f;
        float m01 = ((unsigned)y0 < HH && (unsigned)(x0 + 1) < WW) ? 1.f : 0.f;
        float m10 = ((unsigned)(y0 + 1) < HH && (unsigned)x0 < WW) ? 1.f : 0.f;
        float m11 = ((unsigned)(y0 + 1) < HH && (unsigned)(x0 + 1) < WW) ? 1.f : 0.f;
        int yc0 = min(max(y0, 0), HH - 1), yc1 = min(max(y0 + 1, 0), HH - 1);
        int xc0 = min(max(x0, 0), WW - 1), xc1 = min(max(x0 + 1, 0), WW - 1);
        wt[e] = make_float4((1.f - wy) * (1.f - wx) * m00, (1.f - wy) * wx * m01,
                            wy * (1.f - wx) * m10, wy * wx * m11);
        it[e] = make_ushort4((unsigned short)(yc0 * WW + xc0), (unsigned short)(yc0 * WW + xc1),
                             (unsigned short)(yc1 * WW + xc0), (unsigned short)(yc1 * WW + xc1));
    }
    __syncthreads();

    float acc[2][8][4];
#pragma unroll
    for (int a = 0; a < 2; a++)
#pragma unroll
        for (int b = 0; b < 8; b++)
#pragma unroll
            for (int c = 0; c < 4; c++) acc[a][b][c] = 0.f;

    int wm = wid & 3, wn = wid >> 2;
    int bRow = tid >> 1, bHalf = tid & 1;
    int qtr = lid >> 3;             // pixel within gather group of 4
    int cl4 = lid & 7;              // channel quad within 32-chunk
    const float* xtn = g_xt + (size_t)n * HW * 256;

    // ldmatrix lane-address offsets (within a tile)
    uint32_t aLane = (uint32_t)((wm * 32 + ((lid >> 3) & 1) * 8 + (lid & 7)) * 80 + (lid >> 4) * 16);
    uint32_t bLane = (uint32_t)((wn * 64 + ((lid >> 4) & 1) * 8 + (lid & 7)) * 80 + ((lid >> 3) & 1) * 16);

    auto b_prefetch = [&](int kt, int c0, uint32_t stN) {
        const char* srcH = (const char*)(g_Bh + (size_t)bRow * 2304 + kt * 256 + c0 + bHalf * 16);
        const char* srcL = (const char*)(g_Bl + (size_t)bRow * 2304 + kt * 256 + c0 + bHalf * 16);
        uint32_t dH = sb + stN + O_BH + bRow * 80 + bHalf * 32;
        uint32_t dL = sb + stN + O_BL + bRow * 80 + bHalf * 32;
        cpa16(dH, srcH); cpa16(dH + 16, srcH + 16);
        cpa16(dL, srcL); cpa16(dL + 16, srcL + 16);
        cpa_commit();
    };
    // gather: 8 lanes x float4 cover one pixel-corner's 32 channels (1 wavefront/corner)
    auto gather = [&](int kt, int c0, int iter, float4* r, float4& w4, int& mi) {
        mi = (wid << 3) + (iter << 2) + qtr;
        w4 = wt[kt * BM + mi];
        ushort4 i4 = it[kt * BM + mi];
        const float* xt = xtn + c0 + (cl4 << 2);
        r[0] = *(const float4*)(xt + (size_t)i4.x * 256);
        r[1] = *(const float4*)(xt + (size_t)i4.y * 256);
        r[2] = *(const float4*)(xt + (size_t)i4.z * 256);
        r[3] = *(const float4*)(xt + (size_t)i4.w * 256);
    };
    auto a_put = [&](uint32_t stN, int mi, float4 w4, const float4* r) {
        float v0 = fmaf(w4.x, r[0].x, fmaf(w4.y, r[1].x, fmaf(w4.z, r[2].x, w4.w * r[3].x)));
        float v1 = fmaf(w4.x, r[0].y, fmaf(w4.y, r[1].y, fmaf(w4.z, r[2].y, w4.w * r[3].y)));
        float v2 = fmaf(w4.x, r[0].z, fmaf(w4.y, r[1].z, fmaf(w4.z, r[2].z, w4.w * r[3].z)));
        float v3 = fmaf(w4.x, r[0].w, fmaf(w4.y, r[1].w, fmaf(w4.z, r[2].w, w4.w * r[3].w)));
        __nv_bfloat16 h0 = __float2bfloat16(v0);
        __nv_bfloat16 h1 = __float2bfloat16(v1);
        __nv_bfloat16 h2 = __float2bfloat16(v2);
        __nv_bfloat16 h3 = __float2bfloat16(v3);
        uint32_t off = (uint32_t)(mi * 80) + (uint32_t)(cl4 << 3);
        *(uint2*)(smem + stN + O_AH + off) = make_uint2(pkbf(h0, h1), pkbf(h2, h3));
        *(uint2*)(smem + stN + O_AL + off) =
            make_uint2(pkbf(__float2bfloat16(v0 - __bfloat162float(h0)),
                            __float2bfloat16(v1 - __bfloat162float(h1))),
                       pkbf(__float2bfloat16(v2 - __bfloat162float(h2)),
                            __float2bfloat16(v3 - __bfloat162float(h3))));
    };
    // MMA for one k-step: hoisted A frags, 3 terms
    auto mma_ks = [&](uint32_t stS, int ks) {
        uint32_t aB = sb + stS + aLane + ks * 32;
        uint32_t ah0[4], ah1[4], al0[4], al1[4];
        ldsm4(ah0[0], ah0[1], ah0[2], ah0[3], aB + O_AH);
        ldsm4(ah1[0], ah1[1], ah1[2], ah1[3], aB + O_AH + 16 * 80);
        ldsm4(al0[0], al0[1], al0[2], al0[3], aB + O_AL);
        ldsm4(al1[0], al1[1], al1[2], al1[3], aB + O_AL + 16 * 80);
        uint32_t bB = sb + stS + bLane + ks * 32;
#pragma unroll
        for (int np = 0; np < 4; np++) {
            uint32_t bh[4], bl[4];
            ldsm4(bh[0], bh[1], bh[2], bh[3], bB + O_BH + np * 16 * 80);
            ldsm4(bl[0], bl[1], bl[2], bl[3], bB + O_BL + np * 16 * 80);
            mma_bf16(acc[0][np * 2],     ah0, bh[0], bh[1]);
            mma_bf16(acc[1][np * 2],     ah1, bh[0], bh[1]);
            mma_bf16(acc[0][np * 2 + 1], ah0, bh[2], bh[3]);
            mma_bf16(acc[1][np * 2 + 1], ah1, bh[2], bh[3]);
            mma_bf16(acc[0][np * 2],     ah0, bl[0], bl[1]);
            mma_bf16(acc[1][np * 2],     ah1, bl[0], bl[1]);
            mma_bf16(acc[0][np * 2 + 1], ah0, bl[2], bl[3]);
            mma_bf16(acc[1][np * 2 + 1], ah1, bl[2], bl[3]);
            mma_bf16(acc[0][np * 2],     al0, bh[0], bh[1]);
            mma_bf16(acc[1][np * 2],     al1, bh[0], bh[1]);
            mma_bf16(acc[0][np * 2 + 1], al0, bh[2], bh[3]);
            mma_bf16(acc[1][np * 2 + 1], al1, bh[2], bh[3]);
        }
    };

    // ---- prologue: chunk 0 (kt=0, c0=0) ----
    b_prefetch(0, 0, SM_ST0);
#pragma unroll
    for (int iter = 0; iter < 2; iter++) {
        float4 r[4]; float4 w4; int mi;
        gather(0, 0, iter, r, w4, mi);
        a_put(SM_ST0, mi, w4, r);
    }
    cpa_wait0();
    __syncthreads();

    for (int ch = 0; ch < NCHUNK; ch++) {
        uint32_t stS = SM_ST0 + (uint32_t)(ch & 1) * STAGE_SZ;
        uint32_t stN = SM_ST0 + (uint32_t)((ch & 1) ^ 1) * STAGE_SZ;
        bool pf = (ch + 1 < NCHUNK);
        int ch2 = ch + 1;
        int c2i = ch2 / 9;
        int kt2 = ch2 - c2i * 9, c02 = c2i * 32;

        if (pf) b_prefetch(kt2, c02, stN);

        float4 r0[4]; float4 w40; int mi0 = 0;
        if (pf) gather(kt2, c02, 0, r0, w40, mi0);

        mma_ks(stS, 0);

        if (pf) {
            a_put(stN, mi0, w40, r0);
            gather(kt2, c02, 1, r0, w40, mi0);
        }

        mma_ks(stS, 1);

        if (pf) a_put(stN, mi0, w40, r0);

        cpa_wait0();
        __syncthreads();
    }

    // ---- epilogue: D frags -> g_y[gpix][o] + fused BN stats ----
    float* yb = g_y + (size_t)m0 * 256;
    int g = lid >> 2, c4 = lid & 3;
#pragma unroll
    for (int mt = 0; mt < 2; mt++) {
        int pr = wm * 32 + mt * 16 + g;
#pragma unroll
        for (int nt = 0; nt < 8; nt++) {
            int oc = wn * 64 + nt * 8 + c4 * 2;
            *(float2*)(yb + (size_t)pr * 256 + oc) =
                make_float2(acc[mt][nt][0], acc[mt][nt][1]);
            *(float2*)(yb + (size_t)(pr + 8) * 256 + oc) =
                make_float2(acc[mt][nt][2], acc[mt][nt][3]);
        }
    }
#pragma unroll
    for (int nt = 0; nt < 8; nt++) {
        float s0 = 0.f, s1 = 0.f, q0 = 0.f, q1 = 0.f;
#pragma unroll
        for (int mt = 0; mt < 2; mt++) {
            float a0 = acc[mt][nt][0], a1 = acc[mt][nt][1];
            float a2 = acc[mt][nt][2], a3 = acc[mt][nt][3];
            s0 += a0 + a2;  s1 += a1 + a3;
            q0 = fmaf(a0, a0, fmaf(a2, a2, q0));
            q1 = fmaf(a1, a1, fmaf(a3, a3, q1));
        }
#pragma unroll
        for (int d = 4; d < 32; d <<= 1) {
            s0 += __shfl_xor_sync(0xFFFFFFFFu, s0, d);
            s1 += __shfl_xor_sync(0xFFFFFFFFu, s1, d);
            q0 += __shfl_xor_sync(0xFFFFFFFFu, q0, d);
            q1 += __shfl_xor_sync(0xFFFFFFFFu, q1, d);
        }
        if (lid < 4) {
            int oc = wn * 64 + nt * 8 + lid * 2;
            atomicAdd(&g_sum[oc],     s0);
            atomicAdd(&g_sum[oc + 1], s1);
            atomicAdd(&g_sq[oc],      q0);
            atomicAdd(&g_sq[oc + 1],  q1);
        }
    }
}

// ---------------- kernel 4: BN + ReLU + transpose to NCHW (stats finalized here) ----
__global__ __launch_bounds__(256) void bn_relu_kernel(const float* __restrict__ gamma,
                                                      const float* __restrict__ beta,
                                                      float* __restrict__ out) {
    __shared__ float t[32][33];
    __shared__ float scs[32], shs[32];
    int gp0 = blockIdx.x * 32;
    int o0  = blockIdx.y * 32;
    int tx = threadIdx.x & 31, ty = threadIdx.x >> 5;
    int n  = gp0 / HW;
    int lp0 = gp0 - n * HW;
    if (threadIdx.x < 32) {
        int oo = o0 + threadIdx.x;
        const float inv_n = 1.f / (float)NHW;
        float m = g_sum[oo] * inv_n;
        float v = g_sq[oo] * inv_n - m * m;
        float a = v + 1e-5f;
        float is = rsqrtf(a);
        is = is * (1.5f - 0.5f * a * is * is);
        float sc = is * gamma[oo];
        scs[threadIdx.x] = sc;
        shs[threadIdx.x] = beta[oo] - m * sc;
    }
#pragma unroll
    for (int j = 0; j < 4; j++) {
        int pr = ty + j * 8;
        t[pr][tx] = g_y[(size_t)(gp0 + pr) * 256 + o0 + tx];
    }
    __syncthreads();
#pragma unroll
    for (int j = 0; j < 4; j++) {
        int oi = ty + j * 8;
        int oo = o0 + oi;
        float v = t[tx][oi];
        v = fmaxf(fmaf(v, scs[oi], shs[oi]), 0.f);
        out[((size_t)(n * 256 + oo)) * HW + lp0 + tx] = v;
    }
}

// ---------------- launch ----------------
extern "C" void kernel_launch(void* const* d_in, const int* in_sizes, int n_in,
                              void* d_out, int out_size) {
    const float* x     = (const float*)d_in[0];
    const float* w_off = (const float*)d_in[1];
    const float* b_off = (const float*)d_in[2];
    const float* w_dcn = (const float*)d_in[3];
    const float* gamma = (const float*)d_in[4];
    const float* beta  = (const float*)d_in[5];

    cudaFuncSetAttribute(dcn_gemm_kernel,
                         cudaFuncAttributeMaxDynamicSharedMemorySize, SMEM_GEMM);

    prep_kernel<<<1152, 512>>>(w_dcn, w_off);
    transpose_kernel<<<dim3(HW / 32, CC / 32, NN), 256>>>(x);
    offset_conv_kernel<<<dim3(6, 6, NN), 256>>>(x, b_off);
    dcn_gemm_kernel<<<NHW / BM, NTHR, SMEM_GEMM>>>(x);     // 288 CTAs
    bn_relu_kernel<<<dim3(NHW / 32, 8), 256>>>(gamma, beta, (float*)d_out);
}

// round 13
// speedup vs baseline: 1.4949x; 1.4949x over previous
#include <cuda_runtime.h>
#include <cuda_bf16.h>
#include <cstdint>

#define NN   4
#define CC   256
#define OO   256
#define HH   96
#define WW   96
#define HW   9216
#define NHW  36864

#define BM   128
#define NTHR 512
#define NCHUNK 72           // 9 taps (inner) x 8 c-subchunks (outer)

// GEMM smem (bytes). Tiles use 80B row pitch (40 bf16): ldmatrix 8-row phases
// hit banks {0,20,8,28,16,4,24,12}*4w -> conflict-free. Two pipeline stages.
#define SM_WT    0                      // float4 [9][128]  = 18432
#define SM_IT    18432                  // ushort4[9][128]  =  9216
#define SM_ST0   27648
#define STAGE_SZ 61440                  // AH 10240 | AL 10240 | BH 20480 | BL 20480
#define O_AH 0
#define O_AL 10240
#define O_BH 20480
#define O_BL 40960
#define SMEM_GEMM (SM_ST0 + 2*STAGE_SZ) // 150528

// ---- scratch globals ----
__device__ __align__(256) float         g_off[NN * 18 * HW];
__device__ __align__(256) __nv_bfloat16 g_Bh[OO * 2304];
__device__ __align__(256) __nv_bfloat16 g_Bl[OO * 2304];
__device__ __align__(256) float2        g_wo2[CC * 81];
__device__ __align__(256) float         g_xt[(size_t)NN * HW * 256];  // pixel-major x
__device__ __align__(256) float         g_y[(size_t)NHW * 256];       // [gpix][o]
__device__ float g_sum[OO];
__device__ float g_sq[OO];

// ---- helpers ----
__device__ __forceinline__ uint32_t smem_addr(const void* p) {
    uint32_t a;
    asm("{ .reg .u64 t; cvta.to.shared.u64 t, %1; cvt.u32.u64 %0, t; }" : "=r"(a) : "l"(p));
    return a;
}
__device__ __forceinline__ void cpa16(uint32_t d, const void* s) {
    asm volatile("cp.async.cg.shared.global [%0], [%1], 16;" :: "r"(d), "l"(s) : "memory");
}
__device__ __forceinline__ void cpa8(uint32_t d, const void* s) {
    asm volatile("cp.async.ca.shared.global [%0], [%1], 8;" :: "r"(d), "l"(s) : "memory");
}
__device__ __forceinline__ void cpa4z(uint32_t d, const void* s, int sz) {
    asm volatile("cp.async.ca.shared.global [%0], [%1], 4, %2;" :: "r"(d), "l"(s), "r"(sz) : "memory");
}
__device__ __forceinline__ void cpa_commit() {
    asm volatile("cp.async.commit_group;" ::: "memory");
}
__device__ __forceinline__ void cpa_wait0() {
    asm volatile("cp.async.wait_group 0;" ::: "memory");
}
__device__ __forceinline__ void ldsm4(uint32_t &r0, uint32_t &r1, uint32_t &r2, uint32_t &r3,
                                      uint32_t addr) {
    asm volatile("ldmatrix.sync.aligned.m8n8.x4.shared.b16 {%0,%1,%2,%3}, [%4];"
                 : "=r"(r0), "=r"(r1), "=r"(r2), "=r"(r3) : "r"(addr));
}
__device__ __forceinline__ uint32_t pkbf(__nv_bfloat16 a, __nv_bfloat16 b) {
    return (uint32_t)__bfloat16_as_ushort(a) | ((uint32_t)__bfloat16_as_ushort(b) << 16);
}
__device__ __forceinline__ unsigned long long pack2(float x, float y) {
    unsigned long long r;
    asm("mov.b64 %0, {%1, %2};" : "=l"(r) : "f"(x), "f"(y));
    return r;
}
__device__ __forceinline__ void unpack2(unsigned long long v, float &x, float &y) {
    asm("mov.b64 {%0, %1}, %2;" : "=f"(x), "=f"(y) : "l"(v));
}
__device__ __forceinline__ void ffma2(unsigned long long &d, unsigned long long a,
                                      unsigned long long b) {
    asm("fma.rn.f32x2 %0, %1, %2, %0;" : "+l"(d) : "l"(a), "l"(b));
}
__device__ __forceinline__ void mma_bf16(float* d, const uint32_t* a,
                                         uint32_t b0, uint32_t b1) {
    asm volatile(
        "mma.sync.aligned.m16n8k16.row.col.f32.bf16.bf16.f32 "
        "{%0,%1,%2,%3}, {%4,%5,%6,%7}, {%8,%9}, {%0,%1,%2,%3};"
        : "+f"(d[0]), "+f"(d[1]), "+f"(d[2]), "+f"(d[3])
        : "r"(a[0]), "r"(a[1]), "r"(a[2]), "r"(a[3]), "r"(b0), "r"(b1));
}

// ---------------- kernel 1: weight prep (+ zero BN accumulators) ----------------
__global__ void prep_kernel(const float* __restrict__ w_dcn,
                            const float* __restrict__ w_off) {
    int e = blockIdx.x * blockDim.x + threadIdx.x;   // 589824 exact
    {
        int o = e / 2304, r = e - o * 2304;
        int kt = r >> 8, c = r & 255;
        float v = w_dcn[(o * CC + c) * 9 + kt];
        __nv_bfloat16 hi = __float2bfloat16(v);
        g_Bh[e] = hi;
        g_Bl[e] = __float2bfloat16(v - __bfloat162float(hi));
    }
    if (e < CC * 81) {
        int c = e / 81, r = e - c * 81;
        int t = r / 9, p = r - t * 9;
        g_wo2[e] = make_float2(w_off[(2 * p) * 2304 + c * 9 + t],
                               w_off[(2 * p + 1) * 2304 + c * 9 + t]);
    }
    if (e < OO) { g_sum[e] = 0.f; g_sq[e] = 0.f; }
}

// ---------------- kernel 1b: transpose x -> pixel-major [n][pix][c] ----------------
__global__ __launch_bounds__(256) void transpose_kernel(const float* __restrict__ x) {
    __shared__ float t[32][33];
    int p0 = blockIdx.x * 32;
    int c0 = blockIdx.y * 32;
    int n  = blockIdx.z;
    int tx = threadIdx.x & 31, ty = threadIdx.x >> 5;
#pragma unroll
    for (int j = 0; j < 4; j++) {
        int c = c0 + ty + j * 8;
        t[ty + j * 8][tx] = x[((size_t)(n * CC + c)) * HW + p0 + tx];
    }
    __syncthreads();
#pragma unroll
    for (int j = 0; j < 4; j++) {
        int p = p0 + ty + j * 8;
        g_xt[((size_t)n * HW + p) * 256 + c0 + tx] = t[tx][ty + j * 8];
    }
}

// ---------------- kernel 2: offset conv, cp.async double-buffered ----------------
__global__ __launch_bounds__(256) void offset_conv_kernel(
    const float* __restrict__ x, const float* __restrict__ b_off)
{
    __shared__ float xs[2][4][18][19];
    __shared__ unsigned long long ws[2][4][81];
    int n  = blockIdx.z;
    int h0 = blockIdx.y * 16, w0 = blockIdx.x * 16;
    int tid = threadIdx.x;
    int ty = tid >> 4, tx = tid & 15;
    uint32_t xs_b = smem_addr(&xs[0][0][0][0]);
    uint32_t ws_b = smem_addr(&ws[0][0][0]);
    const unsigned long long* wo2 = (const unsigned long long*)g_wo2;

    unsigned long long acc[9];
#pragma unroll
    for (int p = 0; p < 9; p++) acc[p] = 0ull;

    auto prefetch = [&](int cg, int st) {
        int cb = cg * 4;
        for (int i = tid; i < 1296; i += 256) {
            int cl = i / 324, r2 = i - cl * 324;
            int r = r2 / 18, q = r2 - r * 18;
            int hh = h0 - 1 + r, wp = w0 - 1 + q;
            int ok = ((unsigned)hh < (unsigned)HH && (unsigned)wp < (unsigned)WW) ? 4 : 0;
            int hc = min(max(hh, 0), HH - 1), wc = min(max(wp, 0), WW - 1);
            cpa4z(xs_b + (uint32_t)(((st * 4 + cl) * 342) + r * 19 + q) * 4,
                  &x[((n * CC + cb + cl) * HH + hc) * WW + wc], ok);
        }
        for (int i = tid; i < 324; i += 256) {
            int cl = i / 81, r = i - cl * 81;
            cpa8(ws_b + (uint32_t)((st * 4 + cl) * 81 + r) * 8, &wo2[(cb + cl) * 81 + r]);
        }
        cpa_commit();
    };

    prefetch(0, 0);
    cpa_wait0();
    __syncthreads();

    for (int cg = 0; cg < 64; cg++) {
        int st = cg & 1;
        if (cg < 63) prefetch(cg + 1, st ^ 1);
#pragma unroll
        for (int cl = 0; cl < 4; cl++) {
            float xv[9];
#pragma unroll
            for (int t = 0; t < 9; t++) xv[t] = xs[st][cl][ty + t / 3][tx + t % 3];
#pragma unroll
            for (int t = 0; t < 9; t++) {
                unsigned long long bb = pack2(xv[t], xv[t]);
#pragma unroll
                for (int p = 0; p < 9; p++) ffma2(acc[p], ws[st][cl][t * 9 + p], bb);
            }
        }
        cpa_wait0();
        __syncthreads();
    }
    int h = h0 + ty, w = w0 + tx;
#pragma unroll
    for (int p = 0; p < 9; p++) {
        float a0, a1;
        unpack2(acc[p], a0, a1);
        g_off[((n * 18 + 2 * p) * HH + h) * WW + w]     = a0 + b_off[2 * p];
        g_off[((n * 18 + 2 * p + 1) * HH + h) * WW + w] = a1 + b_off[2 * p + 1];
    }
}

// ---------------- kernel 3: HMMA GEMM, coalesced float2 gather + ldmatrix ----
__global__ __launch_bounds__(NTHR, 1) void dcn_gemm_kernel(const float* __restrict__ X)
{
    extern __shared__ __align__(128) char smem[];
    float4*  wt = (float4*)(smem + SM_WT);
    ushort4* it = (ushort4*)(smem + SM_IT);
    uint32_t sb = smem_addr(smem);

    int tid = threadIdx.x;
    int wid = tid >> 5, lid = tid & 31;
    int m0   = blockIdx.x * BM;
    int n    = m0 / HW;
    int pix0 = m0 - n * HW;

    // ---- bilinear tables ----
    for (int e = tid; e < BM * 9; e += NTHR) {
        int k = e / BM, mi = e - k * BM;
        int pix = pix0 + mi;
        int h = pix / WW, w = pix - h * WW;
        float dy = g_off[((n * 18 + 2 * k) * HH + h) * WW + w];
        float dx = g_off[((n * 18 + 2 * k + 1) * HH + h) * WW + w];
        float py = (float)(h + k / 3 - 1) + dy;
        float px = (float)(w + (k % 3) - 1) + dx;
        float fy = floorf(py), fx = floorf(px);
        int y0 = (int)fy, x0 = (int)fx;
        float wy = py - fy, wx = px - fx;
        float m00 = ((unsigned)y0 < HH && (unsigned)x0 < WW) ? 1.f : 0.f;
        float m01 = ((unsigned)y0 < HH && (unsigned)(x0 + 1) < WW) ? 1.f : 0.f;
        float m10 = ((unsigned)(y0 + 1) < HH && (unsigned)x0 < WW) ? 1.f : 0.f;
        float m11 = ((unsigned)(y0 + 1) < HH && (unsigned)(x0 + 1) < WW) ? 1.f : 0.f;
        int yc0 = min(max(y0, 0), HH - 1), yc1 = min(max(y0 + 1, 0), HH - 1);
        int xc0 = min(max(x0, 0), WW - 1), xc1 = min(max(x0 + 1, 0), WW - 1);
        wt[e] = make_float4((1.f - wy) * (1.f - wx) * m00, (1.f - wy) * wx * m01,
                            wy * (1.f - wx) * m10, wy * wx * m11);
        it[e] = make_ushort4((unsigned short)(yc0 * WW + xc0), (unsigned short)(yc0 * WW + xc1),
                             (unsigned short)(yc1 * WW + xc0), (unsigned short)(yc1 * WW + xc1));
    }
    __syncthreads();

    float acc[2][8][4];
#pragma unroll
    for (int a = 0; a < 2; a++)
#pragma unroll
        for (int b = 0; b < 8; b++)
#pragma unroll
            for (int c = 0; c < 4; c++) acc[a][b][c] = 0.f;

    int wm = wid & 3, wn = wid >> 2;
    int bRow = tid >> 1, bHalf = tid & 1;
    int half = lid >> 4;            // which pixel of the pair
    int cl2  = (lid & 15) << 1;     // channel pair within 32-chunk
    const float* xtn = g_xt + (size_t)n * HW * 256;

    // ldmatrix lane-address offsets (within a tile)
    uint32_t aLane = (uint32_t)((wm * 32 + ((lid >> 3) & 1) * 8 + (lid & 7)) * 80 + (lid >> 4) * 16);
    uint32_t bLane = (uint32_t)((wn * 64 + ((lid >> 4) & 1) * 8 + (lid & 7)) * 80 + ((lid >> 3) & 1) * 16);

    auto b_prefetch = [&](int kt, int c0, uint32_t stN) {
        const char* srcH = (const char*)(g_Bh + (size_t)bRow * 2304 + kt * 256 + c0 + bHalf * 16);
        const char* srcL = (const char*)(g_Bl + (size_t)bRow * 2304 + kt * 256 + c0 + bHalf * 16);
        uint32_t dH = sb + stN + O_BH + bRow * 80 + bHalf * 32;
        uint32_t dL = sb + stN + O_BL + bRow * 80 + bHalf * 32;
        cpa16(dH, srcH); cpa16(dH + 16, srcH + 16);
        cpa16(dL, srcL); cpa16(dL + 16, srcL + 16);
        cpa_commit();
    };
    // gather: iter selects pixel pair; each lane loads float2 (2 channels) per corner
    auto gather = [&](int kt, int c0, int iter, float2* r, float4& w4, int& mi) {
        mi = (wid << 3) + (iter << 1) + half;
        w4 = wt[kt * BM + mi];
        ushort4 i4 = it[kt * BM + mi];
        const float* xt = xtn + c0 + cl2;
        r[0] = *(const float2*)(xt + (size_t)i4.x * 256);
        r[1] = *(const float2*)(xt + (size_t)i4.y * 256);
        r[2] = *(const float2*)(xt + (size_t)i4.z * 256);
        r[3] = *(const float2*)(xt + (size_t)i4.w * 256);
    };
    auto a_put = [&](uint32_t stN, int mi, float4 w4, const float2* r) {
        float v0 = fmaf(w4.x, r[0].x, fmaf(w4.y, r[1].x, fmaf(w4.z, r[2].x, w4.w * r[3].x)));
        float v1 = fmaf(w4.x, r[0].y, fmaf(w4.y, r[1].y, fmaf(w4.z, r[2].y, w4.w * r[3].y)));
        __nv_bfloat16 h0 = __float2bfloat16(v0);
        __nv_bfloat16 h1 = __float2bfloat16(v1);
        uint32_t off = (uint32_t)(mi * 80) + (uint32_t)(cl2 << 1);
        *(uint32_t*)(smem + stN + O_AH + off) = pkbf(h0, h1);
        *(uint32_t*)(smem + stN + O_AL + off) =
            pkbf(__float2bfloat16(v0 - __bfloat162float(h0)),
                 __float2bfloat16(v1 - __bfloat162float(h1)));
    };
    // MMA for one k-step: hoisted A frags, 3 terms
    auto mma_ks = [&](uint32_t stS, int ks) {
        uint32_t aB = sb + stS + aLane + ks * 32;
        uint32_t ah0[4], ah1[4], al0[4], al1[4];
        ldsm4(ah0[0], ah0[1], ah0[2], ah0[3], aB + O_AH);
        ldsm4(ah1[0], ah1[1], ah1[2], ah1[3], aB + O_AH + 16 * 80);
        ldsm4(al0[0], al0[1], al0[2], al0[3], aB + O_AL);
        ldsm4(al1[0], al1[1], al1[2], al1[3], aB + O_AL + 16 * 80);
        uint32_t bB = sb + stS + bLane + ks * 32;
#pragma unroll
        for (int np = 0; np < 4; np++) {
            uint32_t bh[4], bl[4];
            ldsm4(bh[0], bh[1], bh[2], bh[3], bB + O_BH + np * 16 * 80);
            ldsm4(bl[0], bl[1], bl[2], bl[3], bB + O_BL + np * 16 * 80);
            mma_bf16(acc[0][np * 2],     ah0, bh[0], bh[1]);
            mma_bf16(acc[1][np * 2],     ah1, bh[0], bh[1]);
            mma_bf16(acc[0][np * 2 + 1], ah0, bh[2], bh[3]);
            mma_bf16(acc[1][np * 2 + 1], ah1, bh[2], bh[3]);
            mma_bf16(acc[0][np * 2],     ah0, bl[0], bl[1]);
            mma_bf16(acc[1][np * 2],     ah1, bl[0], bl[1]);
            mma_bf16(acc[0][np * 2 + 1], ah0, bl[2], bl[3]);
            mma_bf16(acc[1][np * 2 + 1], ah1, bl[2], bl[3]);
            mma_bf16(acc[0][np * 2],     al0, bh[0], bh[1]);
            mma_bf16(acc[1][np * 2],     al1, bh[0], bh[1]);
            mma_bf16(acc[0][np * 2 + 1], al0, bh[2], bh[3]);
            mma_bf16(acc[1][np * 2 + 1], al1, bh[2], bh[3]);
        }
    };

    // ---- prologue: chunk 0 (kt=0, c0=0) ----
    b_prefetch(0, 0, SM_ST0);
#pragma unroll
    for (int iter = 0; iter < 4; iter++) {
        float2 r[4]; float4 w4; int mi;
        gather(0, 0, iter, r, w4, mi);
        a_put(SM_ST0, mi, w4, r);
    }
    cpa_wait0();
    __syncthreads();

    for (int ch = 0; ch < NCHUNK; ch++) {
        uint32_t stS = SM_ST0 + (uint32_t)(ch & 1) * STAGE_SZ;
        uint32_t stN = SM_ST0 + (uint32_t)((ch & 1) ^ 1) * STAGE_SZ;
        bool pf = (ch + 1 < NCHUNK);
        int ch2 = ch + 1;
        int c2i = ch2 / 9;
        int kt2 = ch2 - c2i * 9, c02 = c2i * 32;

        if (pf) b_prefetch(kt2, c02, stN);

        float2 r0[4], r1[4];
        float4 w40, w41;
        int mi0 = 0, mi1 = 0;
        if (pf) {
            gather(kt2, c02, 0, r0, w40, mi0);
            gather(kt2, c02, 1, r1, w41, mi1);
        }

        mma_ks(stS, 0);

        if (pf) {
            a_put(stN, mi0, w40, r0);
            a_put(stN, mi1, w41, r1);
            gather(kt2, c02, 2, r0, w40, mi0);
            gather(kt2, c02, 3, r1, w41, mi1);
        }

        mma_ks(stS, 1);

        if (pf) {
            a_put(stN, mi0, w40, r0);
            a_put(stN, mi1, w41, r1);
        }

        cpa_wait0();
        __syncthreads();
    }

    // ---- epilogue: D frags -> g_y[gpix][o] + fused BN stats ----
    float* yb = g_y + (size_t)m0 * 256;
    int g = lid >> 2, c4 = lid & 3;
#pragma unroll
    for (int mt = 0; mt < 2; mt++) {
        int pr = wm * 32 + mt * 16 + g;
#pragma unroll
        for (int nt = 0; nt < 8; nt++) {
            int oc = wn * 64 + nt * 8 + c4 * 2;
            *(float2*)(yb + (size_t)pr * 256 + oc) =
                make_float2(acc[mt][nt][0], acc[mt][nt][1]);
            *(float2*)(yb + (size_t)(pr + 8) * 256 + oc) =
                make_float2(acc[mt][nt][2], acc[mt][nt][3]);
        }
    }
#pragma unroll
    for (int nt = 0; nt < 8; nt++) {
        float s0 = 0.f, s1 = 0.f, q0 = 0.f, q1 = 0.f;
#pragma unroll
        for (int mt = 0; mt < 2; mt++) {
            float a0 = acc[mt][nt][0], a1 = acc[mt][nt][1];
            float a2 = acc[mt][nt][2], a3 = acc[mt][nt][3];
            s0 += a0 + a2;  s1 += a1 + a3;
            q0 = fmaf(a0, a0, fmaf(a2, a2, q0));
            q1 = fmaf(a1, a1, fmaf(a3, a3, q1));
        }
#pragma unroll
        for (int d = 4; d < 32; d <<= 1) {
            s0 += __shfl_xor_sync(0xFFFFFFFFu, s0, d);
            s1 += __shfl_xor_sync(0xFFFFFFFFu, s1, d);
            q0 += __shfl_xor_sync(0xFFFFFFFFu, q0, d);
            q1 += __shfl_xor_sync(0xFFFFFFFFu, q1, d);
        }
        if (lid < 4) {
            int oc = wn * 64 + nt * 8 + lid * 2;
            atomicAdd(&g_sum[oc],     s0);
            atomicAdd(&g_sum[oc + 1], s1);
            atomicAdd(&g_sq[oc],      q0);
            atomicAdd(&g_sq[oc + 1],  q1);
        }
    }
}

// ---------------- kernel 4: BN + ReLU + transpose to NCHW (stats finalized here) ----
__global__ __launch_bounds__(256) void bn_relu_kernel(const float* __restrict__ gamma,
                                                      const float* __restrict__ beta,
                                                      float* __restrict__ out) {
    __shared__ float t[32][33];
    __shared__ float scs[32], shs[32];
    int gp0 = blockIdx.x * 32;
    int o0  = blockIdx.y * 32;
    int tx = threadIdx.x & 31, ty = threadIdx.x >> 5;
    int n  = gp0 / HW;
    int lp0 = gp0 - n * HW;
    if (threadIdx.x < 32) {
        int oo = o0 + threadIdx.x;
        const float inv_n = 1.f / (float)NHW;
        float m = g_sum[oo] * inv_n;
        float v = g_sq[oo] * inv_n - m * m;
        float a = v + 1e-5f;
        float is = rsqrtf(a);
        is = is * (1.5f - 0.5f * a * is * is);
        float sc = is * gamma[oo];
        scs[threadIdx.x] = sc;
        shs[threadIdx.x] = beta[oo] - m * sc;
    }
#pragma unroll
    for (int j = 0; j < 4; j++) {
        int pr = ty + j * 8;
        t[pr][tx] = g_y[(size_t)(gp0 + pr) * 256 + o0 + tx];
    }
    __syncthreads();
#pragma unroll
    for (int j = 0; j < 4; j++) {
        int oi = ty + j * 8;
        int oo = o0 + oi;
        float v = t[tx][oi];
        v = fmaxf(fmaf(v, scs[oi], shs[oi]), 0.f);
        out[((size_t)(n * 256 + oo)) * HW + lp0 + tx] = v;
    }
}

// ---------------- launch ----------------
extern "C" void kernel_launch(void* const* d_in, const int* in_sizes, int n_in,
                              void* d_out, int out_size) {
    const float* x     = (const float*)d_in[0];
    const float* w_off = (const float*)d_in[1];
    const float* b_off = (const float*)d_in[2];
    const float* w_dcn = (const float*)d_in[3];
    const float* gamma = (const float*)d_in[4];
    const float* beta  = (const float*)d_in[5];

    cudaFuncSetAttribute(dcn_gemm_kernel,
                         cudaFuncAttributeMaxDynamicSharedMemorySize, SMEM_GEMM);

    prep_kernel<<<1152, 512>>>(w_dcn, w_off);
    transpose_kernel<<<dim3(HW / 32, CC / 32, NN), 256>>>(x);
    offset_conv_kernel<<<dim3(6, 6, NN), 256>>>(x, b_off);
    dcn_gemm_kernel<<<NHW / BM, NTHR, SMEM_GEMM>>>(x);     // 288 CTAs
    bn_relu_kernel<<<dim3(NHW / 32, 8), 256>>>(gamma, beta, (float*)d_out);
}